// round 16
// baseline (speedup 1.0000x reference)
#include <cuda_runtime.h>
#include <cuda_bf16.h>
#include <math.h>
#include <stdint.h>

// Problem constants: L=1024, N=4, E=1024, F=4096, H=16, d=64
#define LL 1024
#define NN 4
#define EE 1024
#define FF 4096
#define HH 16
#define HD 64
#define MM (LL*NN)   // 4096 rows

// ---------------- scratch (static device allocations) ----------------
__device__ float g_tf[MM*EE];                         // LN3 tf32 out
__device__ float g_ff[(size_t)MM*FF];                 // fc1 gelu out (tf32 fp32)
__device__ __nv_bfloat16 g_a3[(size_t)MM * 3 * EE];   // LN bf16 / attn out / enc bf16
__device__ __nv_bfloat16 g_qkv[(size_t)MM * 3 * EE];  // fused qkv / kv bf16 outputs
__device__ __nv_bfloat16 g_qc[(size_t)MM * EE];       // cross-attn q bf16
__device__ __nv_bfloat16 g_wall[(size_t)8 * EE * EE]; // all 8 attn-path weights, bf16
__device__ float g_bcat[3*EE];                        // concatenated bias

// ---------------- portable PTX helpers -------
__device__ __forceinline__ uint32_t smem_u32(const void* p) {
    uint32_t a;
    asm("{ .reg .u64 t; cvta.to.shared.u64 t, %1; cvt.u32.u64 %0, t; }" : "=r"(a) : "l"(p));
    return a;
}

#define SWZ(x) ((x) ^ (((x) >> 3) & 0x70))

#define CP_ASYNC16(dst_u32, src_ptr) \
    asm volatile("cp.async.cg.shared.global [%0], [%1], 16;" \
        :: "r"(dst_u32), "l"(src_ptr) : "memory")
#define CP_COMMIT() asm volatile("cp.async.commit_group;" ::: "memory")
#define CP_WAIT1()  asm volatile("cp.async.wait_group 1;" ::: "memory")
#define CP_WAIT0()  asm volatile("cp.async.wait_group 0;" ::: "memory")

__device__ __forceinline__ void ldsm_x4(uint32_t& r0, uint32_t& r1, uint32_t& r2, uint32_t& r3,
                                        uint32_t addr) {
    asm volatile("ldmatrix.sync.aligned.m8n8.x4.shared.b16 {%0,%1,%2,%3}, [%4];"
        : "=r"(r0), "=r"(r1), "=r"(r2), "=r"(r3) : "r"(addr));
}
__device__ __forceinline__ void ldsm_x2(uint32_t& r0, uint32_t& r1, uint32_t addr) {
    asm volatile("ldmatrix.sync.aligned.m8n8.x2.shared.b16 {%0,%1}, [%2];"
        : "=r"(r0), "=r"(r1) : "r"(addr));
}
__device__ __forceinline__ void mma_bf16(float* d, const uint32_t* a, const uint32_t* b) {
    asm volatile("mma.sync.aligned.m16n8k16.row.col.f32.bf16.bf16.f32 "
        "{%0,%1,%2,%3}, {%4,%5,%6,%7}, {%8,%9}, {%0,%1,%2,%3};"
        : "+f"(d[0]), "+f"(d[1]), "+f"(d[2]), "+f"(d[3])
        : "r"(a[0]), "r"(a[1]), "r"(a[2]), "r"(a[3]), "r"(b[0]), "r"(b[1]));
}
__device__ __forceinline__ void mma_tf32(float* d, const uint32_t* a, const uint32_t* b) {
    asm volatile("mma.sync.aligned.m16n8k8.row.col.f32.tf32.tf32.f32 "
        "{%0,%1,%2,%3}, {%4,%5,%6,%7}, {%8,%9}, {%0,%1,%2,%3};"
        : "+f"(d[0]), "+f"(d[1]), "+f"(d[2]), "+f"(d[3])
        : "r"(a[0]), "r"(a[1]), "r"(a[2]), "r"(a[3]), "r"(b[0]), "r"(b[1]));
}
__device__ __forceinline__ uint32_t pack_bf16x2(float x, float y) {
    __nv_bfloat162 h = __floats2bfloat162_rn(x, y);
    return *(uint32_t*)&h;
}
__device__ __forceinline__ float to_tf32(float x) {
    uint32_t u;
    asm("cvt.rna.tf32.f32 %0, %1;" : "=r"(u) : "f"(x));
    return __uint_as_float(u);
}

// ---------------- layernorm core ----------------
__device__ __forceinline__ void ln_core(const float* __restrict__ x, int row, int tid,
                                        float4& v, float& mean, float& rstd) {
    const float4* xr = (const float4*)(x + (size_t)row * EE);
    v = xr[tid];
    float s  = v.x + v.y + v.z + v.w;
    float sq = v.x*v.x + v.y*v.y + v.z*v.z + v.w*v.w;
    #pragma unroll
    for (int off = 16; off > 0; off >>= 1) {
        s  += __shfl_down_sync(0xffffffffu, s,  off);
        sq += __shfl_down_sync(0xffffffffu, sq, off);
    }
    __shared__ float rs[8], rq[8];
    __shared__ float s_mean, s_rstd;
    int lane = tid & 31, wid = tid >> 5;
    if (lane == 0) { rs[wid] = s; rq[wid] = sq; }
    __syncthreads();
    if (tid == 0) {
        float ts = 0.f, tq = 0.f;
        #pragma unroll
        for (int i = 0; i < 8; i++) { ts += rs[i]; tq += rq[i]; }
        float mn = ts * (1.0f / EE);
        float var = tq * (1.0f / EE) - mn * mn;
        s_mean = mn;
        s_rstd = rsqrtf(var + 1e-5f);
    }
    __syncthreads();
    mean = s_mean; rstd = s_rstd;
}

// LN -> 1-term bf16 (row stride EE)
__global__ void ln_bf16_kernel(const float* __restrict__ x, const float* __restrict__ g,
                               const float* __restrict__ b, __nv_bfloat16* __restrict__ y) {
    int row = blockIdx.x, tid = threadIdx.x;
    float4 v; float mean, rstd;
    ln_core(x, row, tid, v, mean, rstd);
    float4 gv = ((const float4*)g)[tid], bv = ((const float4*)b)[tid];
    float ox = (v.x - mean) * rstd * gv.x + bv.x;
    float oy = (v.y - mean) * rstd * gv.y + bv.y;
    float oz = (v.z - mean) * rstd * gv.z + bv.z;
    float ow = (v.w - mean) * rstd * gv.w + bv.w;
    uint2 pk; pk.x = pack_bf16x2(ox, oy); pk.y = pack_bf16x2(oz, ow);
    *(uint2*)(y + (size_t)row * EE + tid * 4) = pk;
}

// LN -> tf32-rounded fp32 (row stride EE)
__global__ void ln_tf32_kernel(const float* __restrict__ x, const float* __restrict__ g,
                               const float* __restrict__ b, float* __restrict__ y) {
    int row = blockIdx.x, tid = threadIdx.x;
    float4 v; float mean, rstd;
    ln_core(x, row, tid, v, mean, rstd);
    float4 gv = ((const float4*)g)[tid], bv = ((const float4*)b)[tid];
    float4 o;
    o.x = to_tf32((v.x - mean) * rstd * gv.x + bv.x);
    o.y = to_tf32((v.y - mean) * rstd * gv.y + bv.y);
    o.z = to_tf32((v.z - mean) * rstd * gv.z + bv.z);
    o.w = to_tf32((v.w - mean) * rstd * gv.w + bv.w);
    ((float4*)(y + (size_t)row * EE))[tid] = o;
}

// fp32 -> plain bf16 (1-term)
__global__ void conv1_kernel(const float* __restrict__ X, __nv_bfloat16* __restrict__ Y,
                             int total4) {
    int idx = blockIdx.x * blockDim.x + threadIdx.x;
    if (idx >= total4) return;
    float4 v = ((const float4*)X)[idx];
    uint2 pk;
    pk.x = pack_bf16x2(v.x, v.y);
    pk.y = pack_bf16x2(v.z, v.w);
    ((uint2*)Y)[idx] = pk;
}

// 8 fp32 weight matrices -> contiguous bf16 segments (one up-front launch)
__global__ void conv8_kernel(const float* __restrict__ s0, const float* __restrict__ s1,
                             const float* __restrict__ s2, const float* __restrict__ s3,
                             const float* __restrict__ s4, const float* __restrict__ s5,
                             const float* __restrict__ s6, const float* __restrict__ s7,
                             __nv_bfloat16* __restrict__ Y, int per4) {
    int idx = blockIdx.x * blockDim.x + threadIdx.x;
    if (idx >= per4) return;
    int seg = blockIdx.y;
    const float* S;
    switch (seg) {
        case 0: S = s0; break; case 1: S = s1; break;
        case 2: S = s2; break; case 3: S = s3; break;
        case 4: S = s4; break; case 5: S = s5; break;
        case 6: S = s6; break; default: S = s7; break;
    }
    float4 v = ((const float4*)S)[idx];
    uint2 pk;
    pk.x = pack_bf16x2(v.x, v.y);
    pk.y = pack_bf16x2(v.z, v.w);
    ((uint2*)(Y + (size_t)seg * per4 * 4))[idx] = pk;
}

// ---------------- bias concatenation ----------------
__global__ void biascat_kernel(const float* __restrict__ b0, const float* __restrict__ b1,
                               const float* __restrict__ b2, float* __restrict__ out) {
    int seg = blockIdx.x;
    const float* src = seg == 0 ? b0 : (seg == 1 ? b1 : b2);
    out[seg * 1024 + threadIdx.x] = src[threadIdx.x];
}

// ---------------- common tile geometry ----------------
#define GBM 128
#define GBN 128
#define AST (GBM*128)               // A stage bytes (128 rows x 128B)
#define GSTAGE (AST + GBN*128)      // 32768
#define GSMEM (3*GSTAGE + 1024)     // 3 stages; 2 CTAs/SM

// ---------------- HMMA bf16 GEMM (attention path; proven config) ----
// EPI: 1 = bias + residual -> fp32, 4 = bias, x0.125 on cols < qcols -> bf16
template<int EPI>
__global__ void __launch_bounds__(256, 2)
gemm_mma(const __nv_bfloat16* __restrict__ A, const __nv_bfloat16* __restrict__ B,
         const float* __restrict__ bias, const float* __restrict__ R,
         float* __restrict__ C, __nv_bfloat16* __restrict__ C2, int qcols,
         int M, int N, int K) {
    extern __shared__ char dyn_smem[];
    const int tid  = threadIdx.x;
    const int lane = tid & 31;
    const int wid  = tid >> 5;
    const int wm   = wid & 1;
    const int wn   = wid >> 1;
    const int bm = blockIdx.y * GBM;
    const int bn = blockIdx.x * GBN;

    uint32_t raw = smem_u32(dyn_smem);
    uint32_t sb  = (raw + 1023u) & ~1023u;

    const size_t ldb = (size_t)K * 2;
    const char* Abase = (const char*)(A + (size_t)bm * K);
    const char* Bbase = (const char*)(B + (size_t)bn * K);

    auto issue_stage = [&](int kt, int s) {
        uint32_t dst = sb + s * GSTAGE;
        const char* Ab = Abase + (size_t)kt * 128;   // 64 bf16 = 128B
        const char* Bb = Bbase + (size_t)kt * 128;
        #pragma unroll
        for (int p = 0; p < 4; p++) {
            int g   = (p << 8) + tid;
            int row = g >> 3;
            int seg = (g & 7) << 4;
            uint32_t off = SWZ(row * 128 + seg);
            CP_ASYNC16(dst + off,       Ab + (size_t)row * ldb + seg);
            CP_ASYNC16(dst + AST + off, Bb + (size_t)row * ldb + seg);
        }
        CP_COMMIT();
    };

    float acc[4][4][4];
    #pragma unroll
    for (int i = 0; i < 4; i++)
        #pragma unroll
        for (int j = 0; j < 4; j++)
            #pragma unroll
            for (int t = 0; t < 4; t++) acc[i][j][t] = 0.f;

    const int nk = K / 64;
    issue_stage(0, 0);
    issue_stage(1, 1);

    const int a_row = wm * 64 + (lane & 15);
    const int a_kb  = (lane >> 4) << 4;
    const int bp_row = wn * 32 + ((lane >> 4) << 3) + (lane & 7);
    const int bp_kb  = (((lane >> 3) & 1) << 4);

    for (int kt = 0; kt < nk; kt++) {
        if (kt + 1 < nk) { CP_WAIT1(); } else { CP_WAIT0(); }
        __syncthreads();
        if (kt + 2 < nk) issue_stage(kt + 2, (kt + 2) % 3);

        uint32_t ab = sb + (kt % 3) * GSTAGE;
        uint32_t bb = ab + AST;
        #pragma unroll
        for (int kk = 0; kk < 4; kk++) {
            uint32_t af[4][4], bfr[4][2];
            #pragma unroll
            for (int i = 0; i < 4; i++)
                ldsm_x4(af[i][0], af[i][1], af[i][2], af[i][3],
                        ab + SWZ((a_row + i*16) * 128 + kk*32 + a_kb));
            #pragma unroll
            for (int j = 0; j < 2; j++)
                ldsm_x4(bfr[2*j][0], bfr[2*j][1], bfr[2*j+1][0], bfr[2*j+1][1],
                        bb + SWZ((bp_row + j*16) * 128 + kk*32 + bp_kb));
            #pragma unroll
            for (int i = 0; i < 4; i++)
                #pragma unroll
                for (int j = 0; j < 4; j++)
                    mma_bf16(acc[i][j], af[i], bfr[j]);
        }
    }

    const int er = (lane >> 2);
    const int ec = (lane & 3) << 1;
    #pragma unroll
    for (int i = 0; i < 4; i++) {
        #pragma unroll
        for (int j = 0; j < 4; j++) {
            int col = bn + wn*32 + j*8 + ec;
            float bx = bias[col], by = bias[col + 1];
            float sc = (EPI == 4 && col < qcols) ? 0.125f : 1.0f;
            #pragma unroll
            for (int h = 0; h < 2; h++) {
                int row = bm + wm*64 + i*16 + er + h*8;
                float vx = acc[i][j][h*2 + 0] + bx;
                float vy = acc[i][j][h*2 + 1] + by;
                if (EPI == 1) {
                    const float2 rr = *(const float2*)(R + (size_t)row * N + col);
                    vx += rr.x; vy += rr.y;
                }
                if (EPI == 4) {
                    *(uint32_t*)(C2 + (size_t)row * N + col) = pack_bf16x2(vx * sc, vy * sc);
                } else {
                    *(float2*)(C + (size_t)row * N + col) = make_float2(vx, vy);
                }
            }
        }
    }
}

// ---------------- TF32 GEMM (FFN path; 512 threads, 32x32 warp tiles) ----
// 16 warps (4x4), 32x32 warp tile -> acc 32 regs/thread -> fits 64-reg cap at
// (512,2): 32 warps/SM = 8/SMSP for 2x latency cover vs R13's 4/SMSP.
// B = RAW fp32 weights (HW truncates to tf32). 3-stage, single barrier.
// EPI: 1 = bias + residual -> fp32, 3 = bias + gelu -> tf32-rounded fp32
template<int EPI>
__global__ void __launch_bounds__(512, 2)
gemm_tf32(const float* __restrict__ A, const float* __restrict__ B,
          const float* __restrict__ bias, const float* __restrict__ R,
          float* __restrict__ C, int M, int N, int K) {
    extern __shared__ char dyn_smem[];
    const int tid  = threadIdx.x;
    const int lane = tid & 31;
    const int wid  = tid >> 5;          // 0..15
    const int wm   = wid & 3;           // 4 warp rows
    const int wn   = wid >> 2;          // 4 warp cols
    const int bm = blockIdx.y * GBM;
    const int bn = blockIdx.x * GBN;

    uint32_t raw = smem_u32(dyn_smem);
    uint32_t sb  = (raw + 1023u) & ~1023u;

    const size_t ldb = (size_t)K * 4;
    const char* Abase = (const char*)(A + (size_t)bm * K);
    const char* Bbase = (const char*)(B + (size_t)bn * K);

    auto issue_stage = [&](int kt, int s) {
        uint32_t dst = sb + s * GSTAGE;
        const char* Ab = Abase + (size_t)kt * 128;   // 32 fp32 = 128B
        const char* Bb = Bbase + (size_t)kt * 128;
        #pragma unroll
        for (int p = 0; p < 2; p++) {
            int g   = (p << 9) + tid;
            int row = g >> 3;
            int seg = (g & 7) << 4;
            uint32_t off = SWZ(row * 128 + seg);
            CP_ASYNC16(dst + off,       Ab + (size_t)row * ldb + seg);
            CP_ASYNC16(dst + AST + off, Bb + (size_t)row * ldb + seg);
        }
        CP_COMMIT();
    };

    float acc[2][4][4];
    #pragma unroll
    for (int i = 0; i < 2; i++)
        #pragma unroll
        for (int j = 0; j < 4; j++)
            #pragma unroll
            for (int t = 0; t < 4; t++) acc[i][j][t] = 0.f;

    const int nk = K / 32;
    issue_stage(0, 0);
    issue_stage(1, 1);

    // tf32 ldmatrix lane addressing (8x4-tf32 pieces viewed as 8x8 b16)
    const int a_row  = wm * 32 + (lane & 7) + ((lane >> 3) & 1) * 8;
    const int a_colb = ((lane >> 4) & 1) << 4;
    const int b_row  = wn * 32 + (lane & 7) + ((lane >> 4) & 1) * 8;
    const int b_colb = ((lane >> 3) & 1) << 4;

    for (int kt = 0; kt < nk; kt++) {
        if (kt + 1 < nk) { CP_WAIT1(); } else { CP_WAIT0(); }
        __syncthreads();
        if (kt + 2 < nk) issue_stage(kt + 2, (kt + 2) % 3);

        uint32_t ab = sb + (kt % 3) * GSTAGE;
        uint32_t bb = ab + AST;
        #pragma unroll
        for (int kk = 0; kk < 4; kk++) {     // k8 steps within 32-elem chunk
            uint32_t af[2][4], bfr[4][2];
            #pragma unroll
            for (int i = 0; i < 2; i++)
                ldsm_x4(af[i][0], af[i][1], af[i][2], af[i][3],
                        ab + SWZ((a_row + i*16) * 128 + kk*32 + a_colb));
            #pragma unroll
            for (int j = 0; j < 2; j++)
                ldsm_x4(bfr[2*j][0], bfr[2*j][1], bfr[2*j+1][0], bfr[2*j+1][1],
                        bb + SWZ((b_row + j*16) * 128 + kk*32 + b_colb));
            #pragma unroll
            for (int i = 0; i < 2; i++)
                #pragma unroll
                for (int j = 0; j < 4; j++)
                    mma_tf32(acc[i][j], af[i], bfr[j]);
        }
    }

    const int er = (lane >> 2);
    const int ec = (lane & 3) << 1;
    #pragma unroll
    for (int i = 0; i < 2; i++) {
        #pragma unroll
        for (int j = 0; j < 4; j++) {
            int col = bn + wn*32 + j*8 + ec;
            float bx = bias[col], by = bias[col + 1];
            #pragma unroll
            for (int h = 0; h < 2; h++) {
                int row = bm + wm*32 + i*16 + er + h*8;
                float vx = acc[i][j][h*2 + 0] + bx;
                float vy = acc[i][j][h*2 + 1] + by;
                if (EPI == 1) {
                    const float2 rr = *(const float2*)(R + (size_t)row * N + col);
                    vx += rr.x; vy += rr.y;
                } else if (EPI == 3) {
                    vx = to_tf32(0.5f * vx * (1.0f + erff(vx * 0.70710678118654752f)));
                    vy = to_tf32(0.5f * vy * (1.0f + erff(vy * 0.70710678118654752f)));
                }
                *(float2*)(C + (size_t)row * N + col) = make_float2(vx, vy);
            }
        }
    }
}

// ---------------- HMMA flash attention (causal always per reference) ----
// 256 threads, 128-row q-tile (8 warps x 16 rows), 64-row kv-tiles.
__global__ void __launch_bounds__(256)
attn_mma(const __nv_bfloat16* __restrict__ Q, int ldq,
         const __nv_bfloat16* __restrict__ Kp, int ldk,
         const __nv_bfloat16* __restrict__ Vp, int ldv,
         __nv_bfloat16* __restrict__ O) {
    __shared__ __nv_bfloat16 Qs[128*64];
    __shared__ __nv_bfloat16 Ks[64*64];
    __shared__ __nv_bfloat16 Vt[64*64];   // [d][kv]

    const int b = blockIdx.y, qi = blockIdx.x;
    const int n = b >> 4, hh = b & 15;
    const int tid = threadIdx.x, lane = tid & 31, w = tid >> 5;   // w: 0..7
    const int qbase = qi * 128;
    const uint32_t qs = smem_u32(Qs), ks = smem_u32(Ks), vt = smem_u32(Vt);

    for (int i = tid; i < 1024; i += 256) {
        int rr = i >> 3, sb8 = (i & 7) << 4;
        *(uint4*)((char*)Qs + SWZ(rr*128 + sb8)) =
            *(const uint4*)((const char*)(Q + (size_t)((qbase+rr)*NN + n) * ldq + hh*HD) + sb8);
    }

    const int r  = lane >> 2;
    const int cb = (lane & 3) << 1;

    float m0 = -1e30f, m1 = -1e30f, l0 = 0.f, l1 = 0.f;
    float oac[8][4];
    #pragma unroll
    for (int t = 0; t < 8; t++)
        #pragma unroll
        for (int e = 0; e < 4; e++) oac[t][e] = 0.f;

    const int jmax = 2*qi + 1;
    for (int j = 0; j <= jmax; j++) {
        __syncthreads();
        for (int i = tid; i < 512; i += 256) {
            int rr = i >> 3, sb8 = (i & 7) << 4;
            const char* kb = (const char*)(Kp + (size_t)((j*64+rr)*NN + n) * ldk + hh*HD);
            *(uint4*)((char*)Ks + SWZ(rr*128 + sb8)) = *(const uint4*)(kb + sb8);
            const char* vb = (const char*)(Vp + (size_t)((j*64+rr)*NN + n) * ldv + hh*HD);
            uint4 vv = *(const uint4*)(vb + sb8);
            const __nv_bfloat16* ve = (const __nv_bfloat16*)&vv;
            int c0 = (i & 7) << 3;
            #pragma unroll
            for (int e = 0; e < 8; e++)
                *(__nv_bfloat16*)((char*)Vt + SWZ((c0+e)*128 + rr*2)) = ve[e];
        }
        __syncthreads();

        uint32_t af[4][4];
        #pragma unroll
        for (int kk = 0; kk < 4; kk++)
            ldsm_x4(af[kk][0], af[kk][1], af[kk][2], af[kk][3],
                    qs + SWZ((w*16 + (lane & 15))*128 + kk*32 + ((lane >> 4) << 4)));

        float sac[8][4];
        #pragma unroll
        for (int t = 0; t < 8; t++) {
            sac[t][0] = sac[t][1] = sac[t][2] = sac[t][3] = 0.f;
            #pragma unroll
            for (int kk = 0; kk < 4; kk++) {
                uint32_t bfr[2];
                ldsm_x2(bfr[0], bfr[1],
                        ks + SWZ((t*8 + (lane & 7))*128 + kk*32 + (((lane >> 3) & 1) << 4)));
                mma_bf16(sac[t], af[kk], bfr);
            }
        }

        if (j >= 2*qi) {
            int grow0 = qbase + w*16 + r;
            int grow1 = grow0 + 8;
            #pragma unroll
            for (int t = 0; t < 8; t++) {
                int gc = j*64 + t*8 + cb;
                if (gc     > grow0) sac[t][0] = -10000.0f;
                if (gc + 1 > grow0) sac[t][1] = -10000.0f;
                if (gc     > grow1) sac[t][2] = -10000.0f;
                if (gc + 1 > grow1) sac[t][3] = -10000.0f;
            }
        }

        float mx0 = -1e30f, mx1 = -1e30f;
        #pragma unroll
        for (int t = 0; t < 8; t++) {
            mx0 = fmaxf(mx0, fmaxf(sac[t][0], sac[t][1]));
            mx1 = fmaxf(mx1, fmaxf(sac[t][2], sac[t][3]));
        }
        mx0 = fmaxf(mx0, __shfl_xor_sync(0xffffffffu, mx0, 1));
        mx0 = fmaxf(mx0, __shfl_xor_sync(0xffffffffu, mx0, 2));
        mx1 = fmaxf(mx1, __shfl_xor_sync(0xffffffffu, mx1, 1));
        mx1 = fmaxf(mx1, __shfl_xor_sync(0xffffffffu, mx1, 2));
        float mn0 = fmaxf(m0, mx0), mn1 = fmaxf(m1, mx1);
        float al0 = __expf(m0 - mn0), al1 = __expf(m1 - mn1);
        float ls0 = 0.f, ls1 = 0.f;
        #pragma unroll
        for (int t = 0; t < 8; t++) {
            sac[t][0] = __expf(sac[t][0] - mn0);
            sac[t][1] = __expf(sac[t][1] - mn0);
            sac[t][2] = __expf(sac[t][2] - mn1);
            sac[t][3] = __expf(sac[t][3] - mn1);
            ls0 += sac[t][0] + sac[t][1];
            ls1 += sac[t][2] + sac[t][3];
        }
        ls0 += __shfl_xor_sync(0xffffffffu, ls0, 1);
        ls0 += __shfl_xor_sync(0xffffffffu, ls0, 2);
        ls1 += __shfl_xor_sync(0xffffffffu, ls1, 1);
        ls1 += __shfl_xor_sync(0xffffffffu, ls1, 2);
        l0 = l0 * al0 + ls0;  m0 = mn0;
        l1 = l1 * al1 + ls1;  m1 = mn1;
        #pragma unroll
        for (int t = 0; t < 8; t++) {
            oac[t][0] *= al0; oac[t][1] *= al0;
            oac[t][2] *= al1; oac[t][3] *= al1;
        }

        uint32_t pf[4][4];
        #pragma unroll
        for (int kt = 0; kt < 4; kt++) {
            pf[kt][0] = pack_bf16x2(sac[2*kt][0],   sac[2*kt][1]);
            pf[kt][1] = pack_bf16x2(sac[2*kt][2],   sac[2*kt][3]);
            pf[kt][2] = pack_bf16x2(sac[2*kt+1][0], sac[2*kt+1][1]);
            pf[kt][3] = pack_bf16x2(sac[2*kt+1][2], sac[2*kt+1][3]);
        }

        #pragma unroll
        for (int td = 0; td < 8; td++) {
            #pragma unroll
            for (int kt = 0; kt < 4; kt++) {
                uint32_t bfr[2];
                ldsm_x2(bfr[0], bfr[1],
                        vt + SWZ((td*8 + (lane & 7))*128 + kt*32 + (((lane >> 3) & 1) << 4)));
                mma_bf16(oac[td], pf[kt], bfr);
            }
        }
    }

    float inv0 = 1.0f / l0, inv1 = 1.0f / l1;
    int row0 = qbase + w*16 + r;
    int row1 = row0 + 8;
    #pragma unroll
    for (int td = 0; td < 8; td++) {
        int col = td*8 + cb;
        *(uint32_t*)(O + (size_t)(row0*NN + n) * EE + hh*HD + col) =
            pack_bf16x2(oac[td][0]*inv0, oac[td][1]*inv0);
        *(uint32_t*)(O + (size_t)(row1*NN + n) * EE + hh*HD + col) =
            pack_bf16x2(oac[td][2]*inv1, oac[td][3]*inv1);
    }
}

// ---------------- orchestration ----------------
static void conv1(const float* X, __nv_bfloat16* Y, size_t elems) {
    int t4 = (int)(elems / 4);
    conv1_kernel<<<(t4 + 255) / 256, 256>>>(X, Y, t4);
}
static void run_gemm(int epi, const __nv_bfloat16* A, const __nv_bfloat16* B,
                     const float* bias, const float* R, float* C, __nv_bfloat16* C2,
                     int qcols, int M_, int N_, int K_) {
    dim3 grid(N_ / GBN, M_ / GBM);
    if (epi == 1) gemm_mma<1><<<grid, 256, GSMEM>>>(A, B, bias, R, C, C2, qcols, M_, N_, K_);
    else          gemm_mma<4><<<grid, 256, GSMEM>>>(A, B, bias, R, C, C2, qcols, M_, N_, K_);
}
static void run_gemm_tf(int epi, const float* A, const float* B,
                        const float* bias, const float* R, float* C,
                        int M_, int N_, int K_) {
    dim3 grid(N_ / GBN, M_ / GBM);
    if (epi == 1) gemm_tf32<1><<<grid, 512, GSMEM>>>(A, B, bias, R, C, M_, N_, K_);
    else          gemm_tf32<3><<<grid, 512, GSMEM>>>(A, B, bias, R, C, M_, N_, K_);
}

extern "C" void kernel_launch(void* const* d_in, const int* in_sizes, int n_in,
                              void* d_out, int out_size) {
    const float* x    = (const float*)d_in[0];
    const float* enc  = (const float*)d_in[1];
    const float* wq_s = (const float*)d_in[2];
    const float* bq_s = (const float*)d_in[3];
    const float* wk_s = (const float*)d_in[4];
    const float* bk_s = (const float*)d_in[5];
    const float* wv_s = (const float*)d_in[6];
    const float* bv_s = (const float*)d_in[7];
    const float* wo_s = (const float*)d_in[8];
    const float* bo_s = (const float*)d_in[9];
    const float* wq_c = (const float*)d_in[10];
    const float* bq_c = (const float*)d_in[11];
    const float* wk_c = (const float*)d_in[12];
    const float* bk_c = (const float*)d_in[13];
    const float* wv_c = (const float*)d_in[14];
    const float* bv_c = (const float*)d_in[15];
    const float* wo_c = (const float*)d_in[16];
    const float* bo_c = (const float*)d_in[17];
    const float* ln1_g = (const float*)d_in[18];
    const float* ln1_b = (const float*)d_in[19];
    const float* ln2_g = (const float*)d_in[20];
    const float* ln2_b = (const float*)d_in[21];
    const float* ln3_g = (const float*)d_in[22];
    const float* ln3_b = (const float*)d_in[23];
    const float* fc1_w = (const float*)d_in[24];
    const float* fc1_b = (const float*)d_in[25];
    const float* fc2_w = (const float*)d_in[26];
    const float* fc2_b = (const float*)d_in[27];
    float* out = (float*)d_out;

    float *p_tf, *p_ff, *p_bcat;
    __nv_bfloat16 *p_a3, *p_wall, *p_qkv, *p_qc;
    cudaGetSymbolAddress((void**)&p_tf,   g_tf);
    cudaGetSymbolAddress((void**)&p_ff,   g_ff);
    cudaGetSymbolAddress((void**)&p_a3,   g_a3);
    cudaGetSymbolAddress((void**)&p_qkv,  g_qkv);
    cudaGetSymbolAddress((void**)&p_qc,   g_qc);
    cudaGetSymbolAddress((void**)&p_wall, g_wall);
    cudaGetSymbolAddress((void**)&p_bcat, g_bcat);

    cudaFuncSetAttribute(gemm_mma<1>,  cudaFuncAttributeMaxDynamicSharedMemorySize, GSMEM);
    cudaFuncSetAttribute(gemm_mma<4>,  cudaFuncAttributeMaxDynamicSharedMemorySize, GSMEM);
    cudaFuncSetAttribute(gemm_tf32<1>, cudaFuncAttributeMaxDynamicSharedMemorySize, GSMEM);
    cudaFuncSetAttribute(gemm_tf32<3>, cudaFuncAttributeMaxDynamicSharedMemorySize, GSMEM);

    dim3 agrid(LL / 128, NN * HH);   // 8 x 64
    const size_t W1 = (size_t)EE * EE;

    // ---- all 8 attention-path weights -> bf16, one up-front launch ----
    {
        int p4 = (int)(W1 / 4);
        dim3 cg((p4 + 255) / 256, 8);
        conv8_kernel<<<cg, 256>>>(wq_s, wk_s, wv_s, wo_s, wq_c, wk_c, wv_c, wo_c,
                                  p_wall, p4);
    }
    const __nv_bfloat16* w_qkv_s = p_wall;            // segs 0-2 (contiguous N=3072)
    const __nv_bfloat16* w_o_s   = p_wall + 3*W1;
    const __nv_bfloat16* w_q_c   = p_wall + 4*W1;
    const __nv_bfloat16* w_kv_c  = p_wall + 5*W1;     // segs 5-6 (contiguous N=2048)
    const __nv_bfloat16* w_o_c   = p_wall + 7*W1;

    // ---- block 1: self-attention (fused QKV -> bf16 with q pre-scaled) ----
    ln_bf16_kernel<<<MM, 256>>>(x, ln1_g, ln1_b, p_a3);
    biascat_kernel<<<3, 1024>>>(bq_s, bk_s, bv_s, p_bcat);
    run_gemm(4, p_a3, w_qkv_s, p_bcat, nullptr, nullptr, p_qkv, EE, MM, 3*EE, EE);
    attn_mma<<<agrid, 256>>>(p_qkv, 3*EE, p_qkv + EE, 3*EE, p_qkv + 2*EE, 3*EE, p_a3);
    run_gemm(1, p_a3, w_o_s, bo_s, x, out, nullptr, 0, MM, EE, EE);

    // ---- block 2: cross-attention (reference applies causal mask here too) ----
    ln_bf16_kernel<<<MM, 256>>>(out, ln2_g, ln2_b, p_a3);
    run_gemm(4, p_a3, w_q_c, bq_c, nullptr, nullptr, p_qc, EE, MM, EE, EE);
    conv1(enc, p_a3, (size_t)MM * EE);
    biascat_kernel<<<2, 1024>>>(bk_c, bv_c, nullptr, p_bcat);
    run_gemm(4, p_a3, w_kv_c, p_bcat, nullptr, nullptr, p_qkv, 0, MM, 2*EE, EE);
    attn_mma<<<agrid, 256>>>(p_qc, EE, p_qkv, 2*EE, p_qkv + EE, 2*EE, p_a3);
    run_gemm(1, p_a3, w_o_c, bo_c, out, out, nullptr, 0, MM, EE, EE);

    // ---- block 3: FFN (1-term TF32; raw fp32 weights, HW truncation) ----
    ln_tf32_kernel<<<MM, 256>>>(out, ln3_g, ln3_b, p_tf);
    run_gemm_tf(3, p_tf, fc1_w, fc1_b, nullptr, p_ff, MM, FF, EE);
    run_gemm_tf(1, p_ff, fc2_w, fc2_b, out, out, MM, EE, FF);
}

// round 17
// speedup vs baseline: 1.0939x; 1.0939x over previous
#include <cuda_runtime.h>
#include <cuda_bf16.h>
#include <math.h>
#include <stdint.h>

// Problem constants: L=1024, N=4, E=1024, F=4096, H=16, d=64
#define LL 1024
#define NN 4
#define EE 1024
#define FF 4096
#define HH 16
#define HD 64
#define MM (LL*NN)   // 4096 rows

// ---------------- scratch (static device allocations) ----------------
__device__ float g_tf[MM*EE];                          // LN3 tf32 out
__device__ float g_ff[(size_t)MM*FF];                  // fc1 gelu out (tf32 fp32)
__device__ __nv_bfloat16 g_a3[(size_t)MM * 3 * EE];    // LN bf16 / attn out
__device__ __nv_bfloat16 g_qkv[(size_t)MM * 3 * EE];   // fused qkv / kv bf16 outputs
__device__ __nv_bfloat16 g_qc[(size_t)MM * EE];        // cross-attn q bf16
__device__ __nv_bfloat16 g_wall[(size_t)12 * EE * EE]; // 8 weights + enc (4 segs), bf16
__device__ float g_bcat[3*EE];                         // concatenated bias

// ---------------- portable PTX helpers -------
__device__ __forceinline__ uint32_t smem_u32(const void* p) {
    uint32_t a;
    asm("{ .reg .u64 t; cvta.to.shared.u64 t, %1; cvt.u32.u64 %0, t; }" : "=r"(a) : "l"(p));
    return a;
}

#define SWZ(x) ((x) ^ (((x) >> 3) & 0x70))

#define CP_ASYNC16(dst_u32, src_ptr) \
    asm volatile("cp.async.cg.shared.global [%0], [%1], 16;" \
        :: "r"(dst_u32), "l"(src_ptr) : "memory")
#define CP_COMMIT() asm volatile("cp.async.commit_group;" ::: "memory")
#define CP_WAIT1()  asm volatile("cp.async.wait_group 1;" ::: "memory")
#define CP_WAIT0()  asm volatile("cp.async.wait_group 0;" ::: "memory")

__device__ __forceinline__ void ldsm_x4(uint32_t& r0, uint32_t& r1, uint32_t& r2, uint32_t& r3,
                                        uint32_t addr) {
    asm volatile("ldmatrix.sync.aligned.m8n8.x4.shared.b16 {%0,%1,%2,%3}, [%4];"
        : "=r"(r0), "=r"(r1), "=r"(r2), "=r"(r3) : "r"(addr));
}
__device__ __forceinline__ void ldsm_x2(uint32_t& r0, uint32_t& r1, uint32_t addr) {
    asm volatile("ldmatrix.sync.aligned.m8n8.x2.shared.b16 {%0,%1}, [%2];"
        : "=r"(r0), "=r"(r1) : "r"(addr));
}
__device__ __forceinline__ void mma_bf16(float* d, const uint32_t* a, const uint32_t* b) {
    asm volatile("mma.sync.aligned.m16n8k16.row.col.f32.bf16.bf16.f32 "
        "{%0,%1,%2,%3}, {%4,%5,%6,%7}, {%8,%9}, {%0,%1,%2,%3};"
        : "+f"(d[0]), "+f"(d[1]), "+f"(d[2]), "+f"(d[3])
        : "r"(a[0]), "r"(a[1]), "r"(a[2]), "r"(a[3]), "r"(b[0]), "r"(b[1]));
}
__device__ __forceinline__ void mma_tf32(float* d, const uint32_t* a, const uint32_t* b) {
    asm volatile("mma.sync.aligned.m16n8k8.row.col.f32.tf32.tf32.f32 "
        "{%0,%1,%2,%3}, {%4,%5,%6,%7}, {%8,%9}, {%0,%1,%2,%3};"
        : "+f"(d[0]), "+f"(d[1]), "+f"(d[2]), "+f"(d[3])
        : "r"(a[0]), "r"(a[1]), "r"(a[2]), "r"(a[3]), "r"(b[0]), "r"(b[1]));
}
__device__ __forceinline__ uint32_t pack_bf16x2(float x, float y) {
    __nv_bfloat162 h = __floats2bfloat162_rn(x, y);
    return *(uint32_t*)&h;
}
__device__ __forceinline__ float to_tf32(float x) {
    uint32_t u;
    asm("cvt.rna.tf32.f32 %0, %1;" : "=r"(u) : "f"(x));
    return __uint_as_float(u);
}

// ---------------- layernorm core ----------------
__device__ __forceinline__ void ln_core(const float* __restrict__ x, int row, int tid,
                                        float4& v, float& mean, float& rstd) {
    const float4* xr = (const float4*)(x + (size_t)row * EE);
    v = xr[tid];
    float s  = v.x + v.y + v.z + v.w;
    float sq = v.x*v.x + v.y*v.y + v.z*v.z + v.w*v.w;
    #pragma unroll
    for (int off = 16; off > 0; off >>= 1) {
        s  += __shfl_down_sync(0xffffffffu, s,  off);
        sq += __shfl_down_sync(0xffffffffu, sq, off);
    }
    __shared__ float rs[8], rq[8];
    __shared__ float s_mean, s_rstd;
    int lane = tid & 31, wid = tid >> 5;
    if (lane == 0) { rs[wid] = s; rq[wid] = sq; }
    __syncthreads();
    if (tid == 0) {
        float ts = 0.f, tq = 0.f;
        #pragma unroll
        for (int i = 0; i < 8; i++) { ts += rs[i]; tq += rq[i]; }
        float mn = ts * (1.0f / EE);
        float var = tq * (1.0f / EE) - mn * mn;
        s_mean = mn;
        s_rstd = rsqrtf(var + 1e-5f);
    }
    __syncthreads();
    mean = s_mean; rstd = s_rstd;
}

// LN -> 1-term bf16 (row stride EE)
__global__ void ln_bf16_kernel(const float* __restrict__ x, const float* __restrict__ g,
                               const float* __restrict__ b, __nv_bfloat16* __restrict__ y) {
    int row = blockIdx.x, tid = threadIdx.x;
    float4 v; float mean, rstd;
    ln_core(x, row, tid, v, mean, rstd);
    float4 gv = ((const float4*)g)[tid], bv = ((const float4*)b)[tid];
    float ox = (v.x - mean) * rstd * gv.x + bv.x;
    float oy = (v.y - mean) * rstd * gv.y + bv.y;
    float oz = (v.z - mean) * rstd * gv.z + bv.z;
    float ow = (v.w - mean) * rstd * gv.w + bv.w;
    uint2 pk; pk.x = pack_bf16x2(ox, oy); pk.y = pack_bf16x2(oz, ow);
    *(uint2*)(y + (size_t)row * EE + tid * 4) = pk;
}

// LN -> tf32-rounded fp32 (row stride EE)
__global__ void ln_tf32_kernel(const float* __restrict__ x, const float* __restrict__ g,
                               const float* __restrict__ b, float* __restrict__ y) {
    int row = blockIdx.x, tid = threadIdx.x;
    float4 v; float mean, rstd;
    ln_core(x, row, tid, v, mean, rstd);
    float4 gv = ((const float4*)g)[tid], bv = ((const float4*)b)[tid];
    float4 o;
    o.x = to_tf32((v.x - mean) * rstd * gv.x + bv.x);
    o.y = to_tf32((v.y - mean) * rstd * gv.y + bv.y);
    o.z = to_tf32((v.z - mean) * rstd * gv.z + bv.z);
    o.w = to_tf32((v.w - mean) * rstd * gv.w + bv.w);
    ((float4*)(y + (size_t)row * EE))[tid] = o;
}

// 12 fp32 segments -> contiguous bf16 (8 weights + enc split into 4)
__global__ void conv12_kernel(const float* __restrict__ s0, const float* __restrict__ s1,
                              const float* __restrict__ s2, const float* __restrict__ s3,
                              const float* __restrict__ s4, const float* __restrict__ s5,
                              const float* __restrict__ s6, const float* __restrict__ s7,
                              const float* __restrict__ enc,
                              __nv_bfloat16* __restrict__ Y, int per4) {
    int idx = blockIdx.x * blockDim.x + threadIdx.x;
    if (idx >= per4) return;
    int seg = blockIdx.y;
    const float* S;
    switch (seg) {
        case 0: S = s0; break; case 1: S = s1; break;
        case 2: S = s2; break; case 3: S = s3; break;
        case 4: S = s4; break; case 5: S = s5; break;
        case 6: S = s6; break; case 7: S = s7; break;
        default: S = enc + (size_t)(seg - 8) * per4 * 4; break;
    }
    float4 v = ((const float4*)S)[idx];
    uint2 pk;
    pk.x = pack_bf16x2(v.x, v.y);
    pk.y = pack_bf16x2(v.z, v.w);
    ((uint2*)(Y + (size_t)seg * per4 * 4))[idx] = pk;
}

// ---------------- bias concatenation ----------------
__global__ void biascat_kernel(const float* __restrict__ b0, const float* __restrict__ b1,
                               const float* __restrict__ b2, float* __restrict__ out) {
    int seg = blockIdx.x;
    const float* src = seg == 0 ? b0 : (seg == 1 ? b1 : b2);
    out[seg * 1024 + threadIdx.x] = src[threadIdx.x];
}

// ---------------- common tile geometry ----------------
#define GBM 128
#define GBN 128
#define AST (GBM*128)               // A stage bytes (128 rows x 128B)
#define GSTAGE (AST + GBN*128)      // 32768
#define GSMEM (3*GSTAGE + 1024)     // 3 stages; 2 CTAs/SM

// ---------------- HMMA bf16 GEMM (attention path; proven config) ----
// EPI: 1 = bias + residual -> fp32, 4 = bias, x0.125 on cols < qcols -> bf16
template<int EPI>
__global__ void __launch_bounds__(256, 2)
gemm_mma(const __nv_bfloat16* __restrict__ A, const __nv_bfloat16* __restrict__ B,
         const float* __restrict__ bias, const float* __restrict__ R,
         float* __restrict__ C, __nv_bfloat16* __restrict__ C2, int qcols,
         int M, int N, int K) {
    extern __shared__ char dyn_smem[];
    const int tid  = threadIdx.x;
    const int lane = tid & 31;
    const int wid  = tid >> 5;
    const int wm   = wid & 1;
    const int wn   = wid >> 1;
    const int bm = blockIdx.y * GBM;
    const int bn = blockIdx.x * GBN;

    uint32_t raw = smem_u32(dyn_smem);
    uint32_t sb  = (raw + 1023u) & ~1023u;

    const size_t ldb = (size_t)K * 2;
    const char* Abase = (const char*)(A + (size_t)bm * K);
    const char* Bbase = (const char*)(B + (size_t)bn * K);

    auto issue_stage = [&](int kt, int s) {
        uint32_t dst = sb + s * GSTAGE;
        const char* Ab = Abase + (size_t)kt * 128;   // 64 bf16 = 128B
        const char* Bb = Bbase + (size_t)kt * 128;
        #pragma unroll
        for (int p = 0; p < 4; p++) {
            int g   = (p << 8) + tid;
            int row = g >> 3;
            int seg = (g & 7) << 4;
            uint32_t off = SWZ(row * 128 + seg);
            CP_ASYNC16(dst + off,       Ab + (size_t)row * ldb + seg);
            CP_ASYNC16(dst + AST + off, Bb + (size_t)row * ldb + seg);
        }
        CP_COMMIT();
    };

    float acc[4][4][4];
    #pragma unroll
    for (int i = 0; i < 4; i++)
        #pragma unroll
        for (int j = 0; j < 4; j++)
            #pragma unroll
            for (int t = 0; t < 4; t++) acc[i][j][t] = 0.f;

    const int nk = K / 64;
    issue_stage(0, 0);
    issue_stage(1, 1);

    const int a_row = wm * 64 + (lane & 15);
    const int a_kb  = (lane >> 4) << 4;
    const int bp_row = wn * 32 + ((lane >> 4) << 3) + (lane & 7);
    const int bp_kb  = (((lane >> 3) & 1) << 4);

    for (int kt = 0; kt < nk; kt++) {
        if (kt + 1 < nk) { CP_WAIT1(); } else { CP_WAIT0(); }
        __syncthreads();
        if (kt + 2 < nk) issue_stage(kt + 2, (kt + 2) % 3);

        uint32_t ab = sb + (kt % 3) * GSTAGE;
        uint32_t bb = ab + AST;
        #pragma unroll
        for (int kk = 0; kk < 4; kk++) {
            uint32_t af[4][4], bfr[4][2];
            #pragma unroll
            for (int i = 0; i < 4; i++)
                ldsm_x4(af[i][0], af[i][1], af[i][2], af[i][3],
                        ab + SWZ((a_row + i*16) * 128 + kk*32 + a_kb));
            #pragma unroll
            for (int j = 0; j < 2; j++)
                ldsm_x4(bfr[2*j][0], bfr[2*j][1], bfr[2*j+1][0], bfr[2*j+1][1],
                        bb + SWZ((bp_row + j*16) * 128 + kk*32 + bp_kb));
            #pragma unroll
            for (int i = 0; i < 4; i++)
                #pragma unroll
                for (int j = 0; j < 4; j++)
                    mma_bf16(acc[i][j], af[i], bfr[j]);
        }
    }

    const int er = (lane >> 2);
    const int ec = (lane & 3) << 1;
    #pragma unroll
    for (int i = 0; i < 4; i++) {
        #pragma unroll
        for (int j = 0; j < 4; j++) {
            int col = bn + wn*32 + j*8 + ec;
            float bx = bias[col], by = bias[col + 1];
            float sc = (EPI == 4 && col < qcols) ? 0.125f : 1.0f;
            #pragma unroll
            for (int h = 0; h < 2; h++) {
                int row = bm + wm*64 + i*16 + er + h*8;
                float vx = acc[i][j][h*2 + 0] + bx;
                float vy = acc[i][j][h*2 + 1] + by;
                if (EPI == 1) {
                    const float2 rr = *(const float2*)(R + (size_t)row * N + col);
                    vx += rr.x; vy += rr.y;
                }
                if (EPI == 4) {
                    *(uint32_t*)(C2 + (size_t)row * N + col) = pack_bf16x2(vx * sc, vy * sc);
                } else {
                    *(float2*)(C + (size_t)row * N + col) = make_float2(vx, vy);
                }
            }
        }
    }
}

// ---------------- TF32 GEMM (FFN path; PROVEN R13 config) ----
// 256 threads, 2x4 warps, 64x32 warp tile, 3-stage single barrier, 2 CTAs/SM.
// B = RAW fp32 weights (HW truncates to tf32).
// EPI: 1 = bias + residual -> fp32, 3 = bias + gelu -> tf32-rounded fp32
template<int EPI>
__global__ void __launch_bounds__(256, 2)
gemm_tf32(const float* __restrict__ A, const float* __restrict__ B,
          const float* __restrict__ bias, const float* __restrict__ R,
          float* __restrict__ C, int M, int N, int K) {
    extern __shared__ char dyn_smem[];
    const int tid  = threadIdx.x;
    const int lane = tid & 31;
    const int wid  = tid >> 5;
    const int wm   = wid & 1;
    const int wn   = wid >> 1;
    const int bm = blockIdx.y * GBM;
    const int bn = blockIdx.x * GBN;

    uint32_t raw = smem_u32(dyn_smem);
    uint32_t sb  = (raw + 1023u) & ~1023u;

    const size_t ldb = (size_t)K * 4;
    const char* Abase = (const char*)(A + (size_t)bm * K);
    const char* Bbase = (const char*)(B + (size_t)bn * K);

    auto issue_stage = [&](int kt, int s) {
        uint32_t dst = sb + s * GSTAGE;
        const char* Ab = Abase + (size_t)kt * 128;   // 32 fp32 = 128B
        const char* Bb = Bbase + (size_t)kt * 128;
        #pragma unroll
        for (int p = 0; p < 4; p++) {
            int g   = (p << 8) + tid;
            int row = g >> 3;
            int seg = (g & 7) << 4;
            uint32_t off = SWZ(row * 128 + seg);
            CP_ASYNC16(dst + off,       Ab + (size_t)row * ldb + seg);
            CP_ASYNC16(dst + AST + off, Bb + (size_t)row * ldb + seg);
        }
        CP_COMMIT();
    };

    float acc[4][4][4];
    #pragma unroll
    for (int i = 0; i < 4; i++)
        #pragma unroll
        for (int j = 0; j < 4; j++)
            #pragma unroll
            for (int t = 0; t < 4; t++) acc[i][j][t] = 0.f;

    const int nk = K / 32;
    issue_stage(0, 0);
    issue_stage(1, 1);

    const int a_row  = wm * 64 + (lane & 7) + ((lane >> 3) & 1) * 8;
    const int a_colb = ((lane >> 4) & 1) << 4;
    const int b_row  = wn * 32 + (lane & 7) + ((lane >> 4) & 1) * 8;
    const int b_colb = ((lane >> 3) & 1) << 4;

    for (int kt = 0; kt < nk; kt++) {
        if (kt + 1 < nk) { CP_WAIT1(); } else { CP_WAIT0(); }
        __syncthreads();
        if (kt + 2 < nk) issue_stage(kt + 2, (kt + 2) % 3);

        uint32_t ab = sb + (kt % 3) * GSTAGE;
        uint32_t bb = ab + AST;
        #pragma unroll
        for (int kk = 0; kk < 4; kk++) {
            uint32_t af[4][4], bfr[4][2];
            #pragma unroll
            for (int i = 0; i < 4; i++)
                ldsm_x4(af[i][0], af[i][1], af[i][2], af[i][3],
                        ab + SWZ((a_row + i*16) * 128 + kk*32 + a_colb));
            #pragma unroll
            for (int j = 0; j < 2; j++)
                ldsm_x4(bfr[2*j][0], bfr[2*j][1], bfr[2*j+1][0], bfr[2*j+1][1],
                        bb + SWZ((b_row + j*16) * 128 + kk*32 + b_colb));
            #pragma unroll
            for (int i = 0; i < 4; i++)
                #pragma unroll
                for (int j = 0; j < 4; j++)
                    mma_tf32(acc[i][j], af[i], bfr[j]);
        }
    }

    const int er = (lane >> 2);
    const int ec = (lane & 3) << 1;
    #pragma unroll
    for (int i = 0; i < 4; i++) {
        #pragma unroll
        for (int j = 0; j < 4; j++) {
            int col = bn + wn*32 + j*8 + ec;
            float bx = bias[col], by = bias[col + 1];
            #pragma unroll
            for (int h = 0; h < 2; h++) {
                int row = bm + wm*64 + i*16 + er + h*8;
                float vx = acc[i][j][h*2 + 0] + bx;
                float vy = acc[i][j][h*2 + 1] + by;
                if (EPI == 1) {
                    const float2 rr = *(const float2*)(R + (size_t)row * N + col);
                    vx += rr.x; vy += rr.y;
                } else if (EPI == 3) {
                    vx = to_tf32(0.5f * vx * (1.0f + erff(vx * 0.70710678118654752f)));
                    vy = to_tf32(0.5f * vy * (1.0f + erff(vy * 0.70710678118654752f)));
                }
                *(float2*)(C + (size_t)row * N + col) = make_float2(vx, vy);
            }
        }
    }
}

// ---------------- HMMA flash attention (causal always per reference) ----
// 256 threads, 128-row q-tile (8 warps x 16 rows), 64-row kv-tiles.
__global__ void __launch_bounds__(256)
attn_mma(const __nv_bfloat16* __restrict__ Q, int ldq,
         const __nv_bfloat16* __restrict__ Kp, int ldk,
         const __nv_bfloat16* __restrict__ Vp, int ldv,
         __nv_bfloat16* __restrict__ O) {
    __shared__ __nv_bfloat16 Qs[128*64];
    __shared__ __nv_bfloat16 Ks[64*64];
    __shared__ __nv_bfloat16 Vt[64*64];   // [d][kv]

    const int b = blockIdx.y, qi = blockIdx.x;
    const int n = b >> 4, hh = b & 15;
    const int tid = threadIdx.x, lane = tid & 31, w = tid >> 5;   // w: 0..7
    const int qbase = qi * 128;
    const uint32_t qs = smem_u32(Qs), ks = smem_u32(Ks), vt = smem_u32(Vt);

    for (int i = tid; i < 1024; i += 256) {
        int rr = i >> 3, sb8 = (i & 7) << 4;
        *(uint4*)((char*)Qs + SWZ(rr*128 + sb8)) =
            *(const uint4*)((const char*)(Q + (size_t)((qbase+rr)*NN + n) * ldq + hh*HD) + sb8);
    }

    const int r  = lane >> 2;
    const int cb = (lane & 3) << 1;

    float m0 = -1e30f, m1 = -1e30f, l0 = 0.f, l1 = 0.f;
    float oac[8][4];
    #pragma unroll
    for (int t = 0; t < 8; t++)
        #pragma unroll
        for (int e = 0; e < 4; e++) oac[t][e] = 0.f;

    const int jmax = 2*qi + 1;
    for (int j = 0; j <= jmax; j++) {
        __syncthreads();
        for (int i = tid; i < 512; i += 256) {
            int rr = i >> 3, sb8 = (i & 7) << 4;
            const char* kb = (const char*)(Kp + (size_t)((j*64+rr)*NN + n) * ldk + hh*HD);
            *(uint4*)((char*)Ks + SWZ(rr*128 + sb8)) = *(const uint4*)(kb + sb8);
            const char* vb = (const char*)(Vp + (size_t)((j*64+rr)*NN + n) * ldv + hh*HD);
            uint4 vv = *(const uint4*)(vb + sb8);
            const __nv_bfloat16* ve = (const __nv_bfloat16*)&vv;
            int c0 = (i & 7) << 3;
            #pragma unroll
            for (int e = 0; e < 8; e++)
                *(__nv_bfloat16*)((char*)Vt + SWZ((c0+e)*128 + rr*2)) = ve[e];
        }
        __syncthreads();

        uint32_t af[4][4];
        #pragma unroll
        for (int kk = 0; kk < 4; kk++)
            ldsm_x4(af[kk][0], af[kk][1], af[kk][2], af[kk][3],
                    qs + SWZ((w*16 + (lane & 15))*128 + kk*32 + ((lane >> 4) << 4)));

        float sac[8][4];
        #pragma unroll
        for (int t = 0; t < 8; t++) {
            sac[t][0] = sac[t][1] = sac[t][2] = sac[t][3] = 0.f;
            #pragma unroll
            for (int kk = 0; kk < 4; kk++) {
                uint32_t bfr[2];
                ldsm_x2(bfr[0], bfr[1],
                        ks + SWZ((t*8 + (lane & 7))*128 + kk*32 + (((lane >> 3) & 1) << 4)));
                mma_bf16(sac[t], af[kk], bfr);
            }
        }

        if (j >= 2*qi) {
            int grow0 = qbase + w*16 + r;
            int grow1 = grow0 + 8;
            #pragma unroll
            for (int t = 0; t < 8; t++) {
                int gc = j*64 + t*8 + cb;
                if (gc     > grow0) sac[t][0] = -10000.0f;
                if (gc + 1 > grow0) sac[t][1] = -10000.0f;
                if (gc     > grow1) sac[t][2] = -10000.0f;
                if (gc + 1 > grow1) sac[t][3] = -10000.0f;
            }
        }

        float mx0 = -1e30f, mx1 = -1e30f;
        #pragma unroll
        for (int t = 0; t < 8; t++) {
            mx0 = fmaxf(mx0, fmaxf(sac[t][0], sac[t][1]));
            mx1 = fmaxf(mx1, fmaxf(sac[t][2], sac[t][3]));
        }
        mx0 = fmaxf(mx0, __shfl_xor_sync(0xffffffffu, mx0, 1));
        mx0 = fmaxf(mx0, __shfl_xor_sync(0xffffffffu, mx0, 2));
        mx1 = fmaxf(mx1, __shfl_xor_sync(0xffffffffu, mx1, 1));
        mx1 = fmaxf(mx1, __shfl_xor_sync(0xffffffffu, mx1, 2));
        float mn0 = fmaxf(m0, mx0), mn1 = fmaxf(m1, mx1);
        float al0 = __expf(m0 - mn0), al1 = __expf(m1 - mn1);
        float ls0 = 0.f, ls1 = 0.f;
        #pragma unroll
        for (int t = 0; t < 8; t++) {
            sac[t][0] = __expf(sac[t][0] - mn0);
            sac[t][1] = __expf(sac[t][1] - mn0);
            sac[t][2] = __expf(sac[t][2] - mn1);
            sac[t][3] = __expf(sac[t][3] - mn1);
            ls0 += sac[t][0] + sac[t][1];
            ls1 += sac[t][2] + sac[t][3];
        }
        ls0 += __shfl_xor_sync(0xffffffffu, ls0, 1);
        ls0 += __shfl_xor_sync(0xffffffffu, ls0, 2);
        ls1 += __shfl_xor_sync(0xffffffffu, ls1, 1);
        ls1 += __shfl_xor_sync(0xffffffffu, ls1, 2);
        l0 = l0 * al0 + ls0;  m0 = mn0;
        l1 = l1 * al1 + ls1;  m1 = mn1;
        #pragma unroll
        for (int t = 0; t < 8; t++) {
            oac[t][0] *= al0; oac[t][1] *= al0;
            oac[t][2] *= al1; oac[t][3] *= al1;
        }

        uint32_t pf[4][4];
        #pragma unroll
        for (int kt = 0; kt < 4; kt++) {
            pf[kt][0] = pack_bf16x2(sac[2*kt][0],   sac[2*kt][1]);
            pf[kt][1] = pack_bf16x2(sac[2*kt][2],   sac[2*kt][3]);
            pf[kt][2] = pack_bf16x2(sac[2*kt+1][0], sac[2*kt+1][1]);
            pf[kt][3] = pack_bf16x2(sac[2*kt+1][2], sac[2*kt+1][3]);
        }

        #pragma unroll
        for (int td = 0; td < 8; td++) {
            #pragma unroll
            for (int kt = 0; kt < 4; kt++) {
                uint32_t bfr[2];
                ldsm_x2(bfr[0], bfr[1],
                        vt + SWZ((td*8 + (lane & 7))*128 + kt*32 + (((lane >> 3) & 1) << 4)));
                mma_bf16(oac[td], pf[kt], bfr);
            }
        }
    }

    float inv0 = 1.0f / l0, inv1 = 1.0f / l1;
    int row0 = qbase + w*16 + r;
    int row1 = row0 + 8;
    #pragma unroll
    for (int td = 0; td < 8; td++) {
        int col = td*8 + cb;
        *(uint32_t*)(O + (size_t)(row0*NN + n) * EE + hh*HD + col) =
            pack_bf16x2(oac[td][0]*inv0, oac[td][1]*inv0);
        *(uint32_t*)(O + (size_t)(row1*NN + n) * EE + hh*HD + col) =
            pack_bf16x2(oac[td][2]*inv1, oac[td][3]*inv1);
    }
}

// ---------------- orchestration ----------------
static void run_gemm(int epi, const __nv_bfloat16* A, const __nv_bfloat16* B,
                     const float* bias, const float* R, float* C, __nv_bfloat16* C2,
                     int qcols, int M_, int N_, int K_) {
    dim3 grid(N_ / GBN, M_ / GBM);
    if (epi == 1) gemm_mma<1><<<grid, 256, GSMEM>>>(A, B, bias, R, C, C2, qcols, M_, N_, K_);
    else          gemm_mma<4><<<grid, 256, GSMEM>>>(A, B, bias, R, C, C2, qcols, M_, N_, K_);
}
static void run_gemm_tf(int epi, const float* A, const float* B,
                        const float* bias, const float* R, float* C,
                        int M_, int N_, int K_) {
    dim3 grid(N_ / GBN, M_ / GBM);
    if (epi == 1) gemm_tf32<1><<<grid, 256, GSMEM>>>(A, B, bias, R, C, M_, N_, K_);
    else          gemm_tf32<3><<<grid, 256, GSMEM>>>(A, B, bias, R, C, M_, N_, K_);
}

extern "C" void kernel_launch(void* const* d_in, const int* in_sizes, int n_in,
                              void* d_out, int out_size) {
    const float* x    = (const float*)d_in[0];
    const float* enc  = (const float*)d_in[1];
    const float* wq_s = (const float*)d_in[2];
    const float* bq_s = (const float*)d_in[3];
    const float* wk_s = (const float*)d_in[4];
    const float* bk_s = (const float*)d_in[5];
    const float* wv_s = (const float*)d_in[6];
    const float* bv_s = (const float*)d_in[7];
    const float* wo_s = (const float*)d_in[8];
    const float* bo_s = (const float*)d_in[9];
    const float* wq_c = (const float*)d_in[10];
    const float* bq_c = (const float*)d_in[11];
    const float* wk_c = (const float*)d_in[12];
    const float* bk_c = (const float*)d_in[13];
    const float* wv_c = (const float*)d_in[14];
    const float* bv_c = (const float*)d_in[15];
    const float* wo_c = (const float*)d_in[16];
    const float* bo_c = (const float*)d_in[17];
    const float* ln1_g = (const float*)d_in[18];
    const float* ln1_b = (const float*)d_in[19];
    const float* ln2_g = (const float*)d_in[20];
    const float* ln2_b = (const float*)d_in[21];
    const float* ln3_g = (const float*)d_in[22];
    const float* ln3_b = (const float*)d_in[23];
    const float* fc1_w = (const float*)d_in[24];
    const float* fc1_b = (const float*)d_in[25];
    const float* fc2_w = (const float*)d_in[26];
    const float* fc2_b = (const float*)d_in[27];
    float* out = (float*)d_out;

    float *p_tf, *p_ff, *p_bcat;
    __nv_bfloat16 *p_a3, *p_wall, *p_qkv, *p_qc;
    cudaGetSymbolAddress((void**)&p_tf,   g_tf);
    cudaGetSymbolAddress((void**)&p_ff,   g_ff);
    cudaGetSymbolAddress((void**)&p_a3,   g_a3);
    cudaGetSymbolAddress((void**)&p_qkv,  g_qkv);
    cudaGetSymbolAddress((void**)&p_qc,   g_qc);
    cudaGetSymbolAddress((void**)&p_wall, g_wall);
    cudaGetSymbolAddress((void**)&p_bcat, g_bcat);

    cudaFuncSetAttribute(gemm_mma<1>,  cudaFuncAttributeMaxDynamicSharedMemorySize, GSMEM);
    cudaFuncSetAttribute(gemm_mma<4>,  cudaFuncAttributeMaxDynamicSharedMemorySize, GSMEM);
    cudaFuncSetAttribute(gemm_tf32<1>, cudaFuncAttributeMaxDynamicSharedMemorySize, GSMEM);
    cudaFuncSetAttribute(gemm_tf32<3>, cudaFuncAttributeMaxDynamicSharedMemorySize, GSMEM);

    dim3 agrid(LL / 128, NN * HH);   // 8 x 64
    const size_t W1 = (size_t)EE * EE;

    // ---- up-front: 8 attn-path weights + enc -> bf16, one batched launch ----
    // layout: [wq_s|wk_s|wv_s|wo_s|wq_c|wk_c|wv_c|wo_c|enc(4 segs)]
    {
        int p4 = (int)(W1 / 4);
        dim3 cg((p4 + 255) / 256, 12);
        conv12_kernel<<<cg, 256>>>(wq_s, wk_s, wv_s, wo_s, wq_c, wk_c, wv_c, wo_c,
                                   enc, p_wall, p4);
    }
    const __nv_bfloat16* w_qkv_s  = p_wall;           // segs 0-2 (contiguous N=3072)
    const __nv_bfloat16* w_o_s    = p_wall + 3*W1;
    const __nv_bfloat16* w_q_c    = p_wall + 4*W1;
    const __nv_bfloat16* w_kv_c   = p_wall + 5*W1;    // segs 5-6 (contiguous N=2048)
    const __nv_bfloat16* w_o_c    = p_wall + 7*W1;
    const __nv_bfloat16* enc_bf16 = p_wall + 8*W1;    // segs 8-11 (4096 x 1024)

    // ---- block 1: self-attention (fused QKV -> bf16 with q pre-scaled) ----
    ln_bf16_kernel<<<MM, 256>>>(x, ln1_g, ln1_b, p_a3);
    biascat_kernel<<<3, 1024>>>(bq_s, bk_s, bv_s, p_bcat);
    run_gemm(4, p_a3, w_qkv_s, p_bcat, nullptr, nullptr, p_qkv, EE, MM, 3*EE, EE);
    attn_mma<<<agrid, 256>>>(p_qkv, 3*EE, p_qkv + EE, 3*EE, p_qkv + 2*EE, 3*EE, p_a3);
    run_gemm(1, p_a3, w_o_s, bo_s, x, out, nullptr, 0, MM, EE, EE);

    // ---- block 2: cross-attention (reference applies causal mask here too) ----
    ln_bf16_kernel<<<MM, 256>>>(out, ln2_g, ln2_b, p_a3);
    run_gemm(4, p_a3, w_q_c, bq_c, nullptr, nullptr, p_qc, EE, MM, EE, EE);
    biascat_kernel<<<2, 1024>>>(bk_c, bv_c, nullptr, p_bcat);
    run_gemm(4, enc_bf16, w_kv_c, p_bcat, nullptr, nullptr, p_qkv, 0, MM, 2*EE, EE);
    attn_mma<<<agrid, 256>>>(p_qc, EE, p_qkv, 2*EE, p_qkv + EE, 2*EE, p_a3);
    run_gemm(1, p_a3, w_o_c, bo_c, out, out, nullptr, 0, MM, EE, EE);

    // ---- block 3: FFN (1-term TF32; raw fp32 weights, HW truncation) ----
    ln_tf32_kernel<<<MM, 256>>>(out, ln3_g, ln3_b, p_tf);
    run_gemm_tf(3, p_tf, fc1_w, fc1_b, nullptr, p_ff, MM, FF, EE);
    run_gemm_tf(1, p_ff, fc2_w, fc2_b, out, out, MM, EE, FF);
}